// round 5
// baseline (speedup 1.0000x reference)
#include <cuda_runtime.h>
#include <cuda_bf16.h>

// ---------------------------------------------------------------------------
// SplitMemoryModel: B=128, L=2048, H=64, FF=128, D=32, V=64
//
// Pipeline:
//  p1_kernel : per-token  e=embed[seq]; h=LN(e + FFN(e)); k_sem/k_epi (+beta,c)
//              for t<2047, q projections for t==2047. Writes g_k, g_bc, g_q.
//  gram_kernel: per (chain,chunk) strictly-lower L[j][i] = beta_i * (k_j . k_i)
//              in backward-time order, stored transposed for coalesced reads.
//  scan_kernel: per chain (256 warps) backward recurrence via 32-wide chunked
//              forward substitution; accumulates ctx = sum c_t (k.v) k.
//  out_kernel : out = [ctx_s|ctx_e] @ Wo + bo.
//
// Math: M_t = M_{t-1}(I - beta_t k_t k_t^T) + c_t k_t k_t^T, ctx = M_T q.
// => ctx = sum_t c_t (k_t^T u_t) k_t with u_T = q,
//    u_{t-1} = u_t - beta_t (k_t^T u_t) k_t  (exact backward O(D) recurrence).
// Chunked: per 32 backward steps solve (I+L)s = K u_in with
//    L[j][i] = beta_i (k_j . k_i), i<j (strictly lower), then
//    u_out = u_in - K^T diag(beta) s,  ctx += K^T diag(c) s.
// ---------------------------------------------------------------------------

#define FULLMASK 0xffffffffu

// Scratch (device globals; no allocations allowed)
__device__ float  g_k[256][2048][32];      // 67 MB  keys, t=2047 row = 0 pad
__device__ float2 g_bc[256][2048];         // (beta, c); pad = (0,0)
__device__ float  g_LT[256][64][32][32];   // 67 MB  L transposed: [i][j] = L[j][i]
__device__ float  g_q[256][32];
__device__ float  g_ctx[256][32];

// ---------------- shared-memory layout for p1 (in floats) ------------------
#define OFF_EMB   0          // [64][64]
#define OFF_W1T   4096       // [128][68]  W1t[f][c]
#define OFF_W2T   12800      // [64][132]  W2t[d][c]
#define OFF_WST   21248      // [32][68]   Wst[d][c]
#define OFF_WET   23424      // [32][68]
#define OFF_B1    25600      // [128]
#define OFF_B2    25728      // [64]
#define OFF_LNG   25792      // [64]
#define OFF_LNB   25856      // [64]
#define OFF_BS    25920      // [32]
#define OFF_BE    25952      // [32]
#define OFF_WARP  25984      // 8 warps x 2048: e8[8*64] @0, h1b[8*128] @512, hb[8*64] @1536
#define P1_SMEM_FLOATS (25984 + 8*2048)
#define P1_SMEM_BYTES  (P1_SMEM_FLOATS * 4)   // 169,472 B

__global__ void __launch_bounds__(256, 1)
p1_kernel(const int* __restrict__ seq, const float* __restrict__ embed,
          const float* __restrict__ W1, const float* __restrict__ b1v,
          const float* __restrict__ W2, const float* __restrict__ b2v,
          const float* __restrict__ lng, const float* __restrict__ lnb,
          const float* __restrict__ Wsm, const float* __restrict__ bsv,
          const float* __restrict__ Wem, const float* __restrict__ bev)
{
    extern __shared__ float sh[];
    const int tid = threadIdx.x;

    // ---- cooperative weight staging (transposed where needed) ----
    for (int i = tid; i < 4096; i += 256) sh[OFF_EMB + i] = embed[i];
    for (int i = tid; i < 8192; i += 256) {            // W1 [64][128] -> W1t[f][c]
        int c = i >> 7, f = i & 127;
        sh[OFF_W1T + f * 68 + c] = W1[i];
    }
    for (int i = tid; i < 8192; i += 256) {            // W2 [128][64] -> W2t[d][c]
        int c = i >> 6, d = i & 63;
        sh[OFF_W2T + d * 132 + c] = W2[i];
    }
    for (int i = tid; i < 2048; i += 256) {            // Ws/We [64][32] -> [d][c]
        int c = i >> 5, d = i & 31;
        sh[OFF_WST + d * 68 + c] = Wsm[i];
        sh[OFF_WET + d * 68 + c] = Wem[i];
    }
    if (tid < 128) sh[OFF_B1 + tid] = b1v[tid];
    if (tid < 64) { sh[OFF_B2 + tid] = b2v[tid]; sh[OFF_LNG + tid] = lng[tid]; sh[OFF_LNB + tid] = lnb[tid]; }
    if (tid < 32) { sh[OFF_BS + tid] = bsv[tid]; sh[OFF_BE + tid] = bev[tid]; }
    __syncthreads();

    const int warpId = tid >> 5, lane = tid & 31;
    float* wb = &sh[OFF_WARP + warpId * 2048];         // e8 @0, h1b @512, hb @1536
    const float inv2048 = 1.0f / 2048.0f;

    // 32768 tiles of 8 tokens; 8 | 2048 so a tile never crosses a batch row.
    // One persistent wave: 148 blocks x 8 warps = 1184 warp slots, ~28 iters each.
    for (int tile = blockIdx.x * 8 + warpId; tile < 32768; tile += gridDim.x * 8) {
        __syncwarp();
        const int base = tile * 8;           // flat token index
        const int bidx = base >> 11;         // batch
        const int t0   = base & 2047;        // time of token 0 in tile

        // ---- stage A: gather embeddings for 8 tokens into e8 ----
        int sid_l = 0;
        if (lane < 8) sid_l = seq[base + lane];
        #pragma unroll
        for (int p = 0; p < 16; p++) {
            int tok = p >> 1;
            int c   = ((p & 1) << 5) + lane;
            int sid = __shfl_sync(FULLMASK, sid_l, tok);
            wb[tok * 64 + c] = sh[OFF_EMB + sid * 64 + c];
        }
        __syncwarp();

        // ---- stage B: h1 = relu(e @ W1 + b1); lane owns f = lane+32m ----
        float acc[8][4];
        {
            float bb[4];
            #pragma unroll
            for (int m = 0; m < 4; m++) bb[m] = sh[OFF_B1 + lane + 32 * m];
            #pragma unroll
            for (int t = 0; t < 8; t++)
                #pragma unroll
                for (int m = 0; m < 4; m++) acc[t][m] = bb[m];
        }
        #pragma unroll
        for (int cq = 0; cq < 16; cq++) {
            float4 w[4];
            #pragma unroll
            for (int m = 0; m < 4; m++)
                w[m] = *(const float4*)&sh[OFF_W1T + (lane + 32 * m) * 68 + cq * 4];
            #pragma unroll
            for (int t = 0; t < 8; t++) {
                float4 ev = *(const float4*)&wb[t * 64 + cq * 4];
                #pragma unroll
                for (int m = 0; m < 4; m++) {
                    acc[t][m] = fmaf(ev.x, w[m].x, acc[t][m]);
                    acc[t][m] = fmaf(ev.y, w[m].y, acc[t][m]);
                    acc[t][m] = fmaf(ev.z, w[m].z, acc[t][m]);
                    acc[t][m] = fmaf(ev.w, w[m].w, acc[t][m]);
                }
            }
        }
        #pragma unroll
        for (int t = 0; t < 8; t++)
            #pragma unroll
            for (int m = 0; m < 4; m++)
                wb[512 + t * 128 + lane + 32 * m] = fmaxf(acc[t][m], 0.0f);
        __syncwarp();

        // ---- stage C: h2 = h1 @ W2 + b2; lane owns d = lane, lane+32 ----
        float a20[8], a21[8];
        {
            float c0 = sh[OFF_B2 + lane], c1 = sh[OFF_B2 + lane + 32];
            #pragma unroll
            for (int t = 0; t < 8; t++) { a20[t] = c0; a21[t] = c1; }
        }
        #pragma unroll
        for (int cq = 0; cq < 32; cq++) {
            float4 w0 = *(const float4*)&sh[OFF_W2T + lane * 132 + cq * 4];
            float4 w1 = *(const float4*)&sh[OFF_W2T + (lane + 32) * 132 + cq * 4];
            #pragma unroll
            for (int t = 0; t < 8; t++) {
                float4 hv = *(const float4*)&wb[512 + t * 128 + cq * 4];
                a20[t] = fmaf(hv.x, w0.x, a20[t]); a20[t] = fmaf(hv.y, w0.y, a20[t]);
                a20[t] = fmaf(hv.z, w0.z, a20[t]); a20[t] = fmaf(hv.w, w0.w, a20[t]);
                a21[t] = fmaf(hv.x, w1.x, a21[t]); a21[t] = fmaf(hv.y, w1.y, a21[t]);
                a21[t] = fmaf(hv.z, w1.z, a21[t]); a21[t] = fmaf(hv.w, w1.w, a21[t]);
            }
        }

        // ---- stage D: LayerNorm(e + h2) -> hb ----
        #pragma unroll
        for (int t = 0; t < 8; t++) {
            float x0 = wb[t * 64 + lane] + a20[t];
            float x1 = wb[t * 64 + lane + 32] + a21[t];
            float s1 = x0 + x1;
            float s2 = x0 * x0 + x1 * x1;
            #pragma unroll
            for (int o = 16; o > 0; o >>= 1) {
                s1 += __shfl_xor_sync(FULLMASK, s1, o);
                s2 += __shfl_xor_sync(FULLMASK, s2, o);
            }
            float mu  = s1 * (1.0f / 64.0f);
            float var = s2 * (1.0f / 64.0f) - mu * mu;
            float rs  = rsqrtf(var + 1e-5f);
            wb[1536 + t * 64 + lane]      = (x0 - mu) * rs * sh[OFF_LNG + lane]      + sh[OFF_LNB + lane];
            wb[1536 + t * 64 + lane + 32] = (x1 - mu) * rs * sh[OFF_LNG + lane + 32] + sh[OFF_LNB + lane + 32];
        }
        __syncwarp();

        // ---- stage E: k_sem = h@Ws+bs, k_epi = h@We+be; lane owns dim=lane ----
        float as_[8], ae_[8];
        {
            float c0 = sh[OFF_BS + lane], c1 = sh[OFF_BE + lane];
            #pragma unroll
            for (int t = 0; t < 8; t++) { as_[t] = c0; ae_[t] = c1; }
        }
        #pragma unroll
        for (int cq = 0; cq < 16; cq++) {
            float4 ws4 = *(const float4*)&sh[OFF_WST + lane * 68 + cq * 4];
            float4 we4 = *(const float4*)&sh[OFF_WET + lane * 68 + cq * 4];
            #pragma unroll
            for (int t = 0; t < 8; t++) {
                float4 hv = *(const float4*)&wb[1536 + t * 64 + cq * 4];
                as_[t] = fmaf(hv.x, ws4.x, as_[t]); as_[t] = fmaf(hv.y, ws4.y, as_[t]);
                as_[t] = fmaf(hv.z, ws4.z, as_[t]); as_[t] = fmaf(hv.w, ws4.w, as_[t]);
                ae_[t] = fmaf(hv.x, we4.x, ae_[t]); ae_[t] = fmaf(hv.y, we4.y, ae_[t]);
                ae_[t] = fmaf(hv.z, we4.z, ae_[t]); ae_[t] = fmaf(hv.w, we4.w, ae_[t]);
            }
        }

        // ---- per-token epilogue: dens, beta/c, stores ----
        #pragma unroll
        for (int t = 0; t < 8; t++) {
            float ds = as_[t] * as_[t];
            float de = ae_[t] * ae_[t];
            #pragma unroll
            for (int o = 16; o > 0; o >>= 1) {
                ds += __shfl_xor_sync(FULLMASK, ds, o);
                de += __shfl_xor_sync(FULLMASK, de, o);
            }
            const int tg = t0 + t;
            const int chS = 2 * bidx, chE = 2 * bidx + 1;
            if (tg < 2047) {
                g_k[chS][tg][lane] = as_[t];
                g_k[chE][tg][lane] = ae_[t];
                if (lane == 0) {
                    float w = (float)(tg + 1) * inv2048;
                    g_bc[chS][tg] = make_float2(1.0f / (ds + 1e-6f), 1.0f);
                    g_bc[chE][tg] = make_float2(w / (de + 1e-6f), w);
                }
            } else {
                g_q[chS][lane] = as_[t];
                g_q[chE][lane] = ae_[t];
                g_k[chS][2047][lane] = 0.0f;     // pad step: no-op in the scan
                g_k[chE][2047][lane] = 0.0f;
                if (lane == 0) {
                    g_bc[chS][2047] = make_float2(0.0f, 0.0f);
                    g_bc[chE][2047] = make_float2(0.0f, 0.0f);
                }
            }
        }
    }
}

// ---------------------------------------------------------------------------
// Gram kernel: one warp per (chain, chunk). Backward-order index j within a
// chunk maps to time t = 32g + 31 - j. Computes L[j][i] = beta_i*(k_j . k_i)
// for i<j (else 0), stores transposed g_LT[ch][g][i][j] for coalesced reads.
// ---------------------------------------------------------------------------
__global__ void __launch_bounds__(128)
gram_kernel()
{
    __shared__ float shm[4][2240];    // per warp: Ks(32x36) | LsT(32x33) | beta(32)
    const int warpId = threadIdx.x >> 5, lane = threadIdx.x & 31;
    const int wid = blockIdx.x * 4 + warpId;
    const int ch = wid >> 6, g = wid & 63;

    float* Ks  = shm[warpId];
    float* LsT = Ks + 1152;
    float* bet = Ks + 1152 + 1056;

    const float* gk = &g_k[ch][0][0];
    const int tb = g * 32 + 31;

    #pragma unroll 8
    for (int j = 0; j < 32; j++) Ks[j * 36 + lane] = gk[(tb - j) * 32 + lane];
    float2 bc = g_bc[ch][tb - lane];
    bet[lane] = bc.x;
    __syncwarp();

    const int r = lane >> 2, c = lane & 3;  // lane -> 4x8 output block (rows 4r.., cols 8c..)
    float acc[4][8];
    #pragma unroll
    for (int u = 0; u < 4; u++)
        #pragma unroll
        for (int v = 0; v < 8; v++) acc[u][v] = 0.0f;

    #pragma unroll
    for (int lq = 0; lq < 8; lq++) {
        float4 a4[4], b4[8];
        #pragma unroll
        for (int u = 0; u < 4; u++) a4[u] = *(const float4*)&Ks[(4 * r + u) * 36 + lq * 4];
        #pragma unroll
        for (int v = 0; v < 8; v++) b4[v] = *(const float4*)&Ks[(8 * c + v) * 36 + lq * 4];
        #pragma unroll
        for (int u = 0; u < 4; u++)
            #pragma unroll
            for (int v = 0; v < 8; v++) {
                acc[u][v] = fmaf(a4[u].x, b4[v].x, acc[u][v]);
                acc[u][v] = fmaf(a4[u].y, b4[v].y, acc[u][v]);
                acc[u][v] = fmaf(a4[u].z, b4[v].z, acc[u][v]);
                acc[u][v] = fmaf(a4[u].w, b4[v].w, acc[u][v]);
            }
    }

    #pragma unroll
    for (int u = 0; u < 4; u++)
        #pragma unroll
        for (int v = 0; v < 8; v++) {
            int j = 4 * r + u, i = 8 * c + v;
            LsT[i * 33 + j] = (i < j) ? bet[i] * acc[u][v] : 0.0f;
        }
    __syncwarp();

    #pragma unroll 8
    for (int i = 0; i < 32; i++) g_LT[ch][g][i][lane] = LsT[i * 33 + lane];
}

// ---------------------------------------------------------------------------
// Scan kernel: one warp per chain. Backward over 64 chunks of 32 steps.
// Per chunk: b = K v_in;  (I+L) s = b  (31-step shfl forward substitution);
// v -= K^T (beta*s);  ctx += K^T (c*s). Next chunk's K/L prefetched to regs.
// ---------------------------------------------------------------------------
__global__ void __launch_bounds__(32, 1)
scan_kernel()
{
    __shared__ float  Ks[2][32 * 33];
    __shared__ float  vsm[32];
    __shared__ float2 ssm[32];

    const int ch = blockIdx.x, lane = threadIdx.x;
    const float* gk = &g_k[ch][0][0];

    float v   = g_q[ch][lane];
    float ctx = 0.0f;

    float Lreg[32];
    #pragma unroll 8
    for (int j = 0; j < 32; j++) Ks[0][j * 33 + lane] = gk[(2047 - j) * 32 + lane];
    #pragma unroll 8
    for (int i = 0; i < 32; i++) Lreg[i] = g_LT[ch][63][i][lane];
    float2 mybc = g_bc[ch][2047 - lane];
    int buf = 0;

    for (int g = 63; g >= 0; --g) {
        float Kpre[32], Lpre[32];
        float2 bcpre = make_float2(0.0f, 0.0f);
        if (g > 0) {
            const int tb = 32 * (g - 1) + 31;
            #pragma unroll 8
            for (int j = 0; j < 32; j++) Kpre[j] = gk[(tb - j) * 32 + lane];
            #pragma unroll 8
            for (int i = 0; i < 32; i++) Lpre[i] = g_LT[ch][g - 1][i][lane];
            bcpre = g_bc[ch][tb - lane];
        }

        // b_j = k_j . v_in
        vsm[lane] = v;
        __syncwarp();
        const float* kr = &Ks[buf][lane * 33];
        float p0 = 0.0f, p1 = 0.0f, p2 = 0.0f, p3 = 0.0f;
        #pragma unroll
        for (int l = 0; l < 32; l += 4) {
            p0 = fmaf(kr[l + 0], vsm[l + 0], p0);
            p1 = fmaf(kr[l + 1], vsm[l + 1], p1);
            p2 = fmaf(kr[l + 2], vsm[l + 2], p2);
            p3 = fmaf(kr[l + 3], vsm[l + 3], p3);
        }
        float s = (p0 + p1) + (p2 + p3);

        // forward substitution: s_j = b_j - sum_{i<j} L[j][i] s_i
        #pragma unroll
        for (int i = 0; i < 31; i++) {
            float sv = __shfl_sync(FULLMASK, s, i);
            s = fmaf(-Lreg[i], sv, s);
        }

        // scatter beta*s, c*s
        ssm[lane] = make_float2(mybc.x * s, mybc.y * s);
        __syncwarp();

        // v_out and ctx accumulation (column reads, conflict-free)
        #pragma unroll 8
        for (int j = 0; j < 32; j++) {
            float  kv = Ks[buf][j * 33 + lane];
            float2 ps = ssm[j];
            v   = fmaf(-ps.x, kv, v);
            ctx = fmaf( ps.y, kv, ctx);
        }
        __syncwarp();

        if (g > 0) {
            buf ^= 1;
            #pragma unroll 8
            for (int j = 0; j < 32; j++) Ks[buf][j * 33 + lane] = Kpre[j];
            #pragma unroll 8
            for (int i = 0; i < 32; i++) Lreg[i] = Lpre[i];
            mybc = bcpre;
            __syncwarp();
        }
    }
    g_ctx[ch][lane] = ctx;
}

// ---------------------------------------------------------------------------
// Output: out[b][d] = bo[d] + sum_c ctx[b][c] * Wo[c][d]
// g_ctx rows (2b, 2b+1) are exactly the concat [ctx_s | ctx_e].
// ---------------------------------------------------------------------------
__global__ void out_kernel(const float* __restrict__ Wo, const float* __restrict__ bo,
                           float* __restrict__ out)
{
    __shared__ float cs[64];
    const int b = blockIdx.x, d = threadIdx.x;
    cs[d] = (&g_ctx[0][0])[b * 64 + d];
    __syncthreads();
    float o = bo[d];
    #pragma unroll 16
    for (int c = 0; c < 64; c++) o = fmaf(cs[c], Wo[c * 64 + d], o);
    out[b * 64 + d] = o;
}

// ---------------------------------------------------------------------------
extern "C" void kernel_launch(void* const* d_in, const int* in_sizes, int n_in,
                              void* d_out, int out_size)
{
    (void)in_sizes; (void)n_in; (void)out_size;
    const int*   seq   = (const int*)  d_in[0];
    const float* embed = (const float*)d_in[1];
    const float* W1    = (const float*)d_in[2];
    const float* b1v   = (const float*)d_in[3];
    const float* W2    = (const float*)d_in[4];
    const float* b2v   = (const float*)d_in[5];
    const float* lng   = (const float*)d_in[6];
    const float* lnb   = (const float*)d_in[7];
    const float* Wsm   = (const float*)d_in[8];
    const float* bsv   = (const float*)d_in[9];
    const float* Wem   = (const float*)d_in[10];
    const float* bev   = (const float*)d_in[11];
    const float* Wo    = (const float*)d_in[12];
    const float* bo    = (const float*)d_in[13];
    float* out = (float*)d_out;

    // Idempotent, non-stream API: safe under graph capture, no static guards.
    cudaFuncSetAttribute(p1_kernel, cudaFuncAttributeMaxDynamicSharedMemorySize, P1_SMEM_BYTES);

    p1_kernel<<<148, 256, P1_SMEM_BYTES>>>(seq, embed, W1, b1v, W2, b2v,
                                           lng, lnb, Wsm, bsv, Wem, bev);
    gram_kernel<<<4096, 128>>>();
    scan_kernel<<<256, 32>>>();
    out_kernel<<<128, 64>>>(Wo, bo, out);
}

// round 11
// speedup vs baseline: 1.0587x; 1.0587x over previous
#include <cuda_runtime.h>
#include <cuda_bf16.h>

// ---------------------------------------------------------------------------
// SplitMemoryModel: B=128, L=2048, H=64, FF=128, D=32, V=64
//
// Pipeline:
//  p1_kernel : per-token  e=embed[seq]; h=LN(e + FFN(e)); k_sem/k_epi (+beta,c)
//              for t<2047, q projections for t==2047. Writes g_k, g_bc, g_q.
//              GEMM stages use fma.rn.f32x2 packed math (2 lane-FMAs / instr).
//  gram_kernel: per (chain,chunk) strictly-lower L[j][i] = beta_i * (k_j . k_i)
//              in backward-time order, stored transposed for coalesced reads.
//  scan_kernel: per chain (256 warps) backward recurrence via 32-wide chunked
//              forward substitution; accumulates ctx = sum c_t (k.v) k.
//  out_kernel : out = [ctx_s|ctx_e] @ Wo + bo.
//
// Math: M_t = M_{t-1}(I - beta_t k_t k_t^T) + c_t k_t k_t^T, ctx = M_T q.
// => ctx = sum_t c_t (k_t^T u_t) k_t with u_T = q,
//    u_{t-1} = u_t - beta_t (k_t^T u_t) k_t  (exact backward O(D) recurrence).
// Chunked: per 32 backward steps solve (I+L)s = K u_in with
//    L[j][i] = beta_i (k_j . k_i), i<j (strictly lower), then
//    u_out = u_in - K^T diag(beta) s,  ctx += K^T diag(c) s.
// ---------------------------------------------------------------------------

#define FULLMASK 0xffffffffu
typedef unsigned long long u64;

// ---- packed fp32x2 helpers (FFMA2 only reachable via PTX fma.rn.f32x2) ----
__device__ __forceinline__ u64 fma2(u64 a, u64 b, u64 c) {
    u64 d;
    asm("fma.rn.f32x2 %0, %1, %2, %3;" : "=l"(d) : "l"(a), "l"(b), "l"(c));
    return d;
}
__device__ __forceinline__ u64 pack2(float lo, float hi) {
    u64 d; asm("mov.b64 %0, {%1, %2};" : "=l"(d) : "f"(lo), "f"(hi)); return d;
}
__device__ __forceinline__ float hadd2(u64 a) {
    float lo, hi; asm("mov.b64 {%0, %1}, %2;" : "=f"(lo), "=f"(hi) : "l"(a));
    return lo + hi;
}

// Scratch (device globals; no allocations allowed)
__device__ float  g_k[256][2048][32];      // 67 MB  keys, t=2047 row = 0 pad
__device__ float2 g_bc[256][2048];         // (beta, c); pad = (0,0)
__device__ float  g_LT[256][64][32][32];   // 67 MB  L transposed: [i][j] = L[j][i]
__device__ float  g_q[256][32];
__device__ float  g_ctx[256][32];

// ---------------- shared-memory layout for p1 (in floats) ------------------
#define OFF_EMB   0          // [64][64]
#define OFF_W1T   4096       // [128][68]  W1t[f][c]
#define OFF_W2T   12800      // [64][132]  W2t[d][c]
#define OFF_WST   21248      // [32][68]   Wst[d][c]
#define OFF_WET   23424      // [32][68]
#define OFF_B1    25600      // [128]
#define OFF_B2    25728      // [64]
#define OFF_LNG   25792      // [64]
#define OFF_LNB   25856      // [64]
#define OFF_BS    25920      // [32]
#define OFF_BE    25952      // [32]
#define OFF_WARP  25984      // 8 warps x 2048: e8[8*64] @0, h1b[8*128] @512, hb[8*64] @1536
#define P1_SMEM_FLOATS (25984 + 8*2048)
#define P1_SMEM_BYTES  (P1_SMEM_FLOATS * 4)   // 169,472 B

__global__ void __launch_bounds__(256, 1)
p1_kernel(const int* __restrict__ seq, const float* __restrict__ embed,
          const float* __restrict__ W1, const float* __restrict__ b1v,
          const float* __restrict__ W2, const float* __restrict__ b2v,
          const float* __restrict__ lng, const float* __restrict__ lnb,
          const float* __restrict__ Wsm, const float* __restrict__ bsv,
          const float* __restrict__ Wem, const float* __restrict__ bev)
{
    extern __shared__ float sh[];
    const int tid = threadIdx.x;

    // ---- cooperative weight staging (transposed where needed) ----
    for (int i = tid; i < 4096; i += 256) sh[OFF_EMB + i] = embed[i];
    for (int i = tid; i < 8192; i += 256) {            // W1 [64][128] -> W1t[f][c]
        int c = i >> 7, f = i & 127;
        sh[OFF_W1T + f * 68 + c] = W1[i];
    }
    for (int i = tid; i < 8192; i += 256) {            // W2 [128][64] -> W2t[d][c]
        int c = i >> 6, d = i & 63;
        sh[OFF_W2T + d * 132 + c] = W2[i];
    }
    for (int i = tid; i < 2048; i += 256) {            // Ws/We [64][32] -> [d][c]
        int c = i >> 5, d = i & 31;
        sh[OFF_WST + d * 68 + c] = Wsm[i];
        sh[OFF_WET + d * 68 + c] = Wem[i];
    }
    if (tid < 128) sh[OFF_B1 + tid] = b1v[tid];
    if (tid < 64) { sh[OFF_B2 + tid] = b2v[tid]; sh[OFF_LNG + tid] = lng[tid]; sh[OFF_LNB + tid] = lnb[tid]; }
    if (tid < 32) { sh[OFF_BS + tid] = bsv[tid]; sh[OFF_BE + tid] = bev[tid]; }
    __syncthreads();

    const int warpId = tid >> 5, lane = tid & 31;
    float* wb = &sh[OFF_WARP + warpId * 2048];         // e8 @0, h1b @512, hb @1536
    const float inv2048 = 1.0f / 2048.0f;

    // 32768 tiles of 8 tokens; 8 | 2048 so a tile never crosses a batch row.
    // One persistent wave: 148 blocks x 8 warps = 1184 warp slots, ~28 iters each.
    for (int tile = blockIdx.x * 8 + warpId; tile < 32768; tile += gridDim.x * 8) {
        __syncwarp();
        const int base = tile * 8;           // flat token index
        const int bidx = base >> 11;         // batch
        const int t0   = base & 2047;        // time of token 0 in tile

        // ---- stage A: gather embeddings for 8 tokens into e8 ----
        int sid_l = 0;
        if (lane < 8) sid_l = seq[base + lane];
        #pragma unroll
        for (int p = 0; p < 16; p++) {
            int tok = p >> 1;
            int c   = ((p & 1) << 5) + lane;
            int sid = __shfl_sync(FULLMASK, sid_l, tok);
            wb[tok * 64 + c] = sh[OFF_EMB + sid * 64 + c];
        }
        __syncwarp();

        // ---- stage B: h1 = relu(e @ W1 + b1); lane owns f = lane+32m ----
        // acc packs (even-c partial | odd-c partial); bias seeded in lo lane.
        u64 acc[8][4];
        {
            #pragma unroll
            for (int m = 0; m < 4; m++) {
                u64 b0 = pack2(sh[OFF_B1 + lane + 32 * m], 0.0f);
                #pragma unroll
                for (int t = 0; t < 8; t++) acc[t][m] = b0;
            }
        }
        #pragma unroll
        for (int cq = 0; cq < 16; cq++) {
            ulonglong2 w[4];
            #pragma unroll
            for (int m = 0; m < 4; m++)
                w[m] = *(const ulonglong2*)&sh[OFF_W1T + (lane + 32 * m) * 68 + cq * 4];
            #pragma unroll
            for (int t = 0; t < 8; t++) {
                ulonglong2 ev = *(const ulonglong2*)&wb[t * 64 + cq * 4];
                #pragma unroll
                for (int m = 0; m < 4; m++) {
                    acc[t][m] = fma2(ev.x, w[m].x, acc[t][m]);
                    acc[t][m] = fma2(ev.y, w[m].y, acc[t][m]);
                }
            }
        }
        #pragma unroll
        for (int t = 0; t < 8; t++)
            #pragma unroll
            for (int m = 0; m < 4; m++)
                wb[512 + t * 128 + lane + 32 * m] = fmaxf(hadd2(acc[t][m]), 0.0f);
        __syncwarp();

        // ---- stage C: h2 = h1 @ W2 + b2; lane owns d = lane, lane+32 ----
        u64 a20[8], a21[8];
        {
            u64 c0 = pack2(sh[OFF_B2 + lane], 0.0f);
            u64 c1 = pack2(sh[OFF_B2 + lane + 32], 0.0f);
            #pragma unroll
            for (int t = 0; t < 8; t++) { a20[t] = c0; a21[t] = c1; }
        }
        #pragma unroll
        for (int cq = 0; cq < 32; cq++) {
            ulonglong2 w0 = *(const ulonglong2*)&sh[OFF_W2T + lane * 132 + cq * 4];
            ulonglong2 w1 = *(const ulonglong2*)&sh[OFF_W2T + (lane + 32) * 132 + cq * 4];
            #pragma unroll
            for (int t = 0; t < 8; t++) {
                ulonglong2 hv = *(const ulonglong2*)&wb[512 + t * 128 + cq * 4];
                a20[t] = fma2(hv.x, w0.x, a20[t]);
                a20[t] = fma2(hv.y, w0.y, a20[t]);
                a21[t] = fma2(hv.x, w1.x, a21[t]);
                a21[t] = fma2(hv.y, w1.y, a21[t]);
            }
        }

        // ---- stage D: LayerNorm(e + h2) -> hb ----
        #pragma unroll
        for (int t = 0; t < 8; t++) {
            float x0 = wb[t * 64 + lane] + hadd2(a20[t]);
            float x1 = wb[t * 64 + lane + 32] + hadd2(a21[t]);
            float s1 = x0 + x1;
            float s2 = x0 * x0 + x1 * x1;
            #pragma unroll
            for (int o = 16; o > 0; o >>= 1) {
                s1 += __shfl_xor_sync(FULLMASK, s1, o);
                s2 += __shfl_xor_sync(FULLMASK, s2, o);
            }
            float mu  = s1 * (1.0f / 64.0f);
            float var = s2 * (1.0f / 64.0f) - mu * mu;
            float rs  = rsqrtf(var + 1e-5f);
            wb[1536 + t * 64 + lane]      = (x0 - mu) * rs * sh[OFF_LNG + lane]      + sh[OFF_LNB + lane];
            wb[1536 + t * 64 + lane + 32] = (x1 - mu) * rs * sh[OFF_LNG + lane + 32] + sh[OFF_LNB + lane + 32];
        }
        __syncwarp();

        // ---- stage E: k_sem = h@Ws+bs, k_epi = h@We+be; lane owns dim=lane ----
        u64 asp[8], aep[8];
        {
            u64 c0 = pack2(sh[OFF_BS + lane], 0.0f);
            u64 c1 = pack2(sh[OFF_BE + lane], 0.0f);
            #pragma unroll
            for (int t = 0; t < 8; t++) { asp[t] = c0; aep[t] = c1; }
        }
        #pragma unroll
        for (int cq = 0; cq < 16; cq++) {
            ulonglong2 ws4 = *(const ulonglong2*)&sh[OFF_WST + lane * 68 + cq * 4];
            ulonglong2 we4 = *(const ulonglong2*)&sh[OFF_WET + lane * 68 + cq * 4];
            #pragma unroll
            for (int t = 0; t < 8; t++) {
                ulonglong2 hv = *(const ulonglong2*)&wb[1536 + t * 64 + cq * 4];
                asp[t] = fma2(hv.x, ws4.x, asp[t]);
                asp[t] = fma2(hv.y, ws4.y, asp[t]);
                aep[t] = fma2(hv.x, we4.x, aep[t]);
                aep[t] = fma2(hv.y, we4.y, aep[t]);
            }
        }
        float as_[8], ae_[8];
        #pragma unroll
        for (int t = 0; t < 8; t++) { as_[t] = hadd2(asp[t]); ae_[t] = hadd2(aep[t]); }

        // ---- per-token epilogue: dens, beta/c, stores ----
        #pragma unroll
        for (int t = 0; t < 8; t++) {
            float ds = as_[t] * as_[t];
            float de = ae_[t] * ae_[t];
            #pragma unroll
            for (int o = 16; o > 0; o >>= 1) {
                ds += __shfl_xor_sync(FULLMASK, ds, o);
                de += __shfl_xor_sync(FULLMASK, de, o);
            }
            const int tg = t0 + t;
            const int chS = 2 * bidx, chE = 2 * bidx + 1;
            if (tg < 2047) {
                g_k[chS][tg][lane] = as_[t];
                g_k[chE][tg][lane] = ae_[t];
                if (lane == 0) {
                    float w = (float)(tg + 1) * inv2048;
                    g_bc[chS][tg] = make_float2(1.0f / (ds + 1e-6f), 1.0f);
                    g_bc[chE][tg] = make_float2(w / (de + 1e-6f), w);
                }
            } else {
                g_q[chS][lane] = as_[t];
                g_q[chE][lane] = ae_[t];
                g_k[chS][2047][lane] = 0.0f;     // pad step: no-op in the scan
                g_k[chE][2047][lane] = 0.0f;
                if (lane == 0) {
                    g_bc[chS][2047] = make_float2(0.0f, 0.0f);
                    g_bc[chE][2047] = make_float2(0.0f, 0.0f);
                }
            }
        }
    }
}

// ---------------------------------------------------------------------------
// Gram kernel: one warp per (chain, chunk). Backward-order index j within a
// chunk maps to time t = 32g + 31 - j. Computes L[j][i] = beta_i*(k_j . k_i)
// for i<j (else 0), stores transposed g_LT[ch][g][i][j] for coalesced reads.
// ---------------------------------------------------------------------------
__global__ void __launch_bounds__(128)
gram_kernel()
{
    __shared__ float shm[4][2240];    // per warp: Ks(32x36) | LsT(32x33) | beta(32)
    const int warpId = threadIdx.x >> 5, lane = threadIdx.x & 31;
    const int wid = blockIdx.x * 4 + warpId;
    const int ch = wid >> 6, g = wid & 63;

    float* Ks  = shm[warpId];
    float* LsT = Ks + 1152;
    float* bet = Ks + 1152 + 1056;

    const float* gk = &g_k[ch][0][0];
    const int tb = g * 32 + 31;

    #pragma unroll 8
    for (int j = 0; j < 32; j++) Ks[j * 36 + lane] = gk[(tb - j) * 32 + lane];
    float2 bc = g_bc[ch][tb - lane];
    bet[lane] = bc.x;
    __syncwarp();

    const int r = lane >> 2, c = lane & 3;  // lane -> 4x8 output block (rows 4r.., cols 8c..)
    float acc[4][8];
    #pragma unroll
    for (int u = 0; u < 4; u++)
        #pragma unroll
        for (int v = 0; v < 8; v++) acc[u][v] = 0.0f;

    #pragma unroll
    for (int lq = 0; lq < 8; lq++) {
        float4 a4[4], b4[8];
        #pragma unroll
        for (int u = 0; u < 4; u++) a4[u] = *(const float4*)&Ks[(4 * r + u) * 36 + lq * 4];
        #pragma unroll
        for (int v = 0; v < 8; v++) b4[v] = *(const float4*)&Ks[(8 * c + v) * 36 + lq * 4];
        #pragma unroll
        for (int u = 0; u < 4; u++)
            #pragma unroll
            for (int v = 0; v < 8; v++) {
                acc[u][v] = fmaf(a4[u].x, b4[v].x, acc[u][v]);
                acc[u][v] = fmaf(a4[u].y, b4[v].y, acc[u][v]);
                acc[u][v] = fmaf(a4[u].z, b4[v].z, acc[u][v]);
                acc[u][v] = fmaf(a4[u].w, b4[v].w, acc[u][v]);
            }
    }

    #pragma unroll
    for (int u = 0; u < 4; u++)
        #pragma unroll
        for (int v = 0; v < 8; v++) {
            int j = 4 * r + u, i = 8 * c + v;
            LsT[i * 33 + j] = (i < j) ? bet[i] * acc[u][v] : 0.0f;
        }
    __syncwarp();

    #pragma unroll 8
    for (int i = 0; i < 32; i++) g_LT[ch][g][i][lane] = LsT[i * 33 + lane];
}

// ---------------------------------------------------------------------------
// Scan kernel: one warp per chain. Backward over 64 chunks of 32 steps.
// Per chunk: b = K v_in;  (I+L) s = b  (31-step shfl forward substitution);
// v -= K^T (beta*s);  ctx += K^T (c*s). Next chunk's K/L prefetched to regs.
// ---------------------------------------------------------------------------
__global__ void __launch_bounds__(32, 1)
scan_kernel()
{
    __shared__ float  Ks[2][32 * 33];
    __shared__ float  vsm[32];
    __shared__ float2 ssm[32];

    const int ch = blockIdx.x, lane = threadIdx.x;
    const float* gk = &g_k[ch][0][0];

    float v   = g_q[ch][lane];
    float ctx = 0.0f;

    float Lreg[32];
    #pragma unroll 8
    for (int j = 0; j < 32; j++) Ks[0][j * 33 + lane] = gk[(2047 - j) * 32 + lane];
    #pragma unroll 8
    for (int i = 0; i < 32; i++) Lreg[i] = g_LT[ch][63][i][lane];
    float2 mybc = g_bc[ch][2047 - lane];
    int buf = 0;

    for (int g = 63; g >= 0; --g) {
        float Kpre[32], Lpre[32];
        float2 bcpre = make_float2(0.0f, 0.0f);
        if (g > 0) {
            const int tb = 32 * (g - 1) + 31;
            #pragma unroll 8
            for (int j = 0; j < 32; j++) Kpre[j] = gk[(tb - j) * 32 + lane];
            #pragma unroll 8
            for (int i = 0; i < 32; i++) Lpre[i] = g_LT[ch][g - 1][i][lane];
            bcpre = g_bc[ch][tb - lane];
        }

        // b_j = k_j . v_in
        vsm[lane] = v;
        __syncwarp();
        const float* kr = &Ks[buf][lane * 33];
        float p0 = 0.0f, p1 = 0.0f, p2 = 0.0f, p3 = 0.0f;
        #pragma unroll
        for (int l = 0; l < 32; l += 4) {
            p0 = fmaf(kr[l + 0], vsm[l + 0], p0);
            p1 = fmaf(kr[l + 1], vsm[l + 1], p1);
            p2 = fmaf(kr[l + 2], vsm[l + 2], p2);
            p3 = fmaf(kr[l + 3], vsm[l + 3], p3);
        }
        float s = (p0 + p1) + (p2 + p3);

        // forward substitution: s_j = b_j - sum_{i<j} L[j][i] s_i
        #pragma unroll
        for (int i = 0; i < 31; i++) {
            float sv = __shfl_sync(FULLMASK, s, i);
            s = fmaf(-Lreg[i], sv, s);
        }

        // scatter beta*s, c*s
        ssm[lane] = make_float2(mybc.x * s, mybc.y * s);
        __syncwarp();

        // v_out and ctx accumulation (column reads, conflict-free)
        #pragma unroll 8
        for (int j = 0; j < 32; j++) {
            float  kv = Ks[buf][j * 33 + lane];
            float2 ps = ssm[j];
            v   = fmaf(-ps.x, kv, v);
            ctx = fmaf( ps.y, kv, ctx);
        }
        __syncwarp();

        if (g > 0) {
            buf ^= 1;
            #pragma unroll 8
            for (int j = 0; j < 32; j++) Ks[buf][j * 33 + lane] = Kpre[j];
            #pragma unroll 8
            for (int i = 0; i < 32; i++) Lreg[i] = Lpre[i];
            mybc = bcpre;
            __syncwarp();
        }
    }
    g_ctx[ch][lane] = ctx;
}

// ---------------------------------------------------------------------------
// Output: out[b][d] = bo[d] + sum_c ctx[b][c] * Wo[c][d]
// g_ctx rows (2b, 2b+1) are exactly the concat [ctx_s | ctx_e].
// ---------------------------------------------------------------------------
__global__ void out_kernel(const float* __restrict__ Wo, const float* __restrict__ bo,
                           float* __restrict__ out)
{
    __shared__ float cs[64];
    const int b = blockIdx.x, d = threadIdx.x;
    cs[d] = (&g_ctx[0][0])[b * 64 + d];
    __syncthreads();
    float o = bo[d];
    #pragma unroll 16
    for (int c = 0; c < 64; c++) o = fmaf(cs[c], Wo[c * 64 + d], o);
    out[b * 64 + d] = o;
}

// ---------------------------------------------------------------------------
extern "C" void kernel_launch(void* const* d_in, const int* in_sizes, int n_in,
                              void* d_out, int out_size)
{
    (void)in_sizes; (void)n_in; (void)out_size;
    const int*   seq   = (const int*)  d_in[0];
    const float* embed = (const float*)d_in[1];
    const float* W1    = (const float*)d_in[2];
    const float* b1v   = (const float*)d_in[3];
    const float* W2    = (const float*)d_in[4];
    const float* b2v   = (const float*)d_in[5];
    const float* lng   = (const float*)d_in[6];
    const float* lnb   = (const float*)d_in[7];
    const float* Wsm   = (const float*)d_in[8];
    const float* bsv   = (const float*)d_in[9];
    const float* Wem   = (const float*)d_in[10];
    const float* bev   = (const float*)d_in[11];
    const float* Wo    = (const float*)d_in[12];
    const float* bo    = (const float*)d_in[13];
    float* out = (float*)d_out;

    // Idempotent, non-stream API: safe under graph capture, no static guards.
    cudaFuncSetAttribute(p1_kernel, cudaFuncAttributeMaxDynamicSharedMemorySize, P1_SMEM_BYTES);

    p1_kernel<<<148, 256, P1_SMEM_BYTES>>>(seq, embed, W1, b1v, W2, b2v,
                                           lng, lnb, Wsm, bsv, Wem, bev);
    gram_kernel<<<4096, 128>>>();
    scan_kernel<<<256, 32>>>();
    out_kernel<<<128, 64>>>(Wo, bo, out);
}